// round 1
// baseline (speedup 1.0000x reference)
#include <cuda_runtime.h>
#include <math.h>

// Problem constants (match reference_code)
#define NN 50000
#define NE 800000
#define NC 64          // hidden channels
#define CIN 128        // input channels
#define COUT 1024      // output channels
#define NSTEPS 4
#define H2 0.01f       // H*H, H=0.1

// ---------------------------------------------------------------------------
// Scratch (no allocations allowed -> __device__ globals)
// ---------------------------------------------------------------------------
__device__ float g_deg[NN];
__device__ float g_dinv2[NN];
__device__ int   g_cnt[NN];
__device__ int   g_rowptr[NN + 1];
__device__ int   g_cursor[NN];
__device__ int   g_adj[2 * NE];
__device__ float g_xa[(size_t)NC * NN];
__device__ float g_xb[(size_t)NC * NN];
__device__ float g_xc[(size_t)NC * NN];

__device__ __forceinline__ float* buf_sel(int w) {
    return (w == 0) ? g_xa : ((w == 1) ? g_xb : g_xc);
}

// ---------------------------------------------------------------------------
// 1) init: deg = 1 (self loop), cnt = 0
// ---------------------------------------------------------------------------
__global__ void k_init(int n) {
    int i = blockIdx.x * blockDim.x + threadIdx.x;
    if (i < n) {
        g_deg[i] = 1.0f;
        g_cnt[i] = 0;
    }
}

// ---------------------------------------------------------------------------
// 2) per-edge: deg histogram over J (gcn_norm degrees), incidence counts for CSR
// ---------------------------------------------------------------------------
__global__ void k_edge_count(const int* __restrict__ ei, const int* __restrict__ ej, int e) {
    int k = blockIdx.x * blockDim.x + threadIdx.x;
    if (k < e) {
        int i = ei[k], j = ej[k];
        atomicAdd(&g_deg[j], 1.0f);
        atomicAdd(&g_cnt[i], 1);
        atomicAdd(&g_cnt[j], 1);
    }
}

// ---------------------------------------------------------------------------
// 3) dinv2 = 1/deg  (deg >= 1 always, so dinv = rsqrt(deg), dinv^2 = 1/deg)
// ---------------------------------------------------------------------------
__global__ void k_dinv2(int n) {
    int i = blockIdx.x * blockDim.x + threadIdx.x;
    if (i < n) g_dinv2[i] = 1.0f / g_deg[i];
}

// ---------------------------------------------------------------------------
// 4) single-block exclusive scan of cnt -> rowptr (+ cursor copy)
// ---------------------------------------------------------------------------
__global__ void k_scan(int n) {
    __shared__ int s[1024];
    const int CH = (NN + 1023) / 1024;  // 49
    int t = threadIdx.x;
    int base = t * CH;
    int sum = 0;
    for (int k = 0; k < CH; k++) {
        int idx = base + k;
        if (idx < n) sum += g_cnt[idx];
    }
    s[t] = sum;
    __syncthreads();
    // Hillis-Steele inclusive scan over 1024 partials
    for (int off = 1; off < 1024; off <<= 1) {
        int v = 0;
        if (t >= off) v = s[t - off];
        __syncthreads();
        s[t] += v;
        __syncthreads();
    }
    int run = (t == 0) ? 0 : s[t - 1];
    for (int k = 0; k < CH; k++) {
        int idx = base + k;
        if (idx < n) {
            g_rowptr[idx] = run;
            g_cursor[idx] = run;
            run += g_cnt[idx];
        }
    }
    if (t == 0) g_rowptr[n] = s[1023];
}

// ---------------------------------------------------------------------------
// 5) fill undirected adjacency
// ---------------------------------------------------------------------------
__global__ void k_fill(const int* __restrict__ ei, const int* __restrict__ ej, int e) {
    int k = blockIdx.x * blockDim.x + threadIdx.x;
    if (k < e) {
        int i = ei[k], j = ej[k];
        int p = atomicAdd(&g_cursor[i], 1);
        g_adj[p] = j;
        int q = atomicAdd(&g_cursor[j], 1);
        g_adj[q] = i;
    }
}

// ---------------------------------------------------------------------------
// 6) opening: x0[n,o] = relu( sum_c K1[o,c] * xn[c,n] ), write to xa and xb
//    xn is [CIN, N] channel-major (input layout); x stored node-major [N, NC].
// ---------------------------------------------------------------------------
__global__ void k_open(const float* __restrict__ xn, const float* __restrict__ K1, int n) {
    __shared__ float Ks[NC * CIN];  // 32 KB, broadcast reads only
    for (int idx = threadIdx.x; idx < NC * CIN; idx += blockDim.x)
        Ks[idx] = K1[idx];
    __syncthreads();

    int node = blockIdx.x * blockDim.x + threadIdx.x;
    if (node >= n) return;

    float acc[NC];
#pragma unroll
    for (int o = 0; o < NC; o++) acc[o] = 0.0f;

    for (int c = 0; c < CIN; c++) {
        float xv = xn[(size_t)c * n + node];
#pragma unroll
        for (int o = 0; o < NC; o++)
            acc[o] = fmaf(Ks[o * CIN + c], xv, acc[o]);
    }
    size_t base = (size_t)node * NC;
#pragma unroll
    for (int o = 0; o < NC; o++) {
        float v = fmaxf(acc[o], 0.0f);
        g_xa[base + o] = v;
        g_xb[base + o] = v;
    }
}

// ---------------------------------------------------------------------------
// 7) fused wave step:
//    lap[n,c] = dinv2[n] * ( (sum_m dinv2[m]) * x[n,c] - sum_m dinv2[m]*x[m,c] )
//    x_next[n,c] = 2*x[n,c] - x_prev[n,c] - H2 * tanh( sum_k K[c,k]*lap[n,k] )
//    One warp per node; 64x64 matvec via padded smem K.
// ---------------------------------------------------------------------------
__global__ void k_step(int wcur, int wprev, int wnext, const float* __restrict__ K, int n) {
    __shared__ float Ks[NC * 65];   // padded: row o at Ks[o*65 + c], conflict-free
    __shared__ float laps[8][NC];

    const float* xc = buf_sel(wcur);
    const float* xp = buf_sel(wprev);
    float* xo = buf_sel(wnext);

    for (int idx = threadIdx.x; idx < NC * NC; idx += blockDim.x)
        Ks[(idx >> 6) * 65 + (idx & 63)] = K[idx];
    __syncthreads();

    int warp = threadIdx.x >> 5;
    int lane = threadIdx.x & 31;

    for (int base = blockIdx.x * 8; base < n; base += gridDim.x * 8) {
        int node = base + warp;
        if (node < n) {
            size_t nb = (size_t)node * NC;
            float x0 = xc[nb + lane];
            float x1 = xc[nb + 32 + lane];
            int r0 = g_rowptr[node];
            int r1 = g_rowptr[node + 1];

            float acc0 = 0.0f, acc1 = 0.0f, ss = 0.0f;
            for (int kk = r0; kk < r1; kk += 32) {
                int rem = r1 - kk;
                int a = 0;
                if (lane < rem) a = g_adj[kk + lane];
                int cnt = rem < 32 ? rem : 32;
#pragma unroll 4
                for (int t = 0; t < cnt; ++t) {
                    int m = __shfl_sync(0xffffffffu, a, t);
                    float w = g_dinv2[m];
                    const float* xm = xc + (size_t)m * NC;
                    acc0 = fmaf(w, xm[lane], acc0);
                    acc1 = fmaf(w, xm[32 + lane], acc1);
                    ss += w;
                }
            }
            float di = g_dinv2[node];
            float lap0 = di * fmaf(ss, x0, -acc0);
            float lap1 = di * fmaf(ss, x1, -acc1);

            laps[warp][lane] = lap0;
            laps[warp][lane + 32] = lap1;
            __syncwarp();

            float t0 = 0.0f, t1 = 0.0f;
#pragma unroll
            for (int c = 0; c < NC; c++) {
                float lv = laps[warp][c];
                t0 = fmaf(Ks[lane * 65 + c], lv, t0);
                t1 = fmaf(Ks[(lane + 32) * 65 + c], lv, t1);
            }
            __syncwarp();

            float d0 = tanhf(t0);
            float d1 = tanhf(t1);
            xo[nb + lane]      = fmaf(2.0f, x0, -xp[nb + lane]) - H2 * d0;
            xo[nb + 32 + lane] = fmaf(2.0f, x1, -xp[nb + 32 + lane]) - H2 * d1;
        }
    }
}

// ---------------------------------------------------------------------------
// 8) closing projection: out[o, n] = sum_c KNclose[o,c] * x[n,c]
//    16 output tiles of 64; K tile in padded smem; x via L1 (64 KB/256 nodes).
// ---------------------------------------------------------------------------
__global__ void k_close(int wfin, const float* __restrict__ KN, float* __restrict__ out, int n) {
    __shared__ float Ks[NC * 65];
    const float* x = buf_sel(wfin);
    int node = blockIdx.x * blockDim.x + threadIdx.x;

    for (int ot = 0; ot < COUT / NC; ot++) {
        for (int idx = threadIdx.x; idx < NC * NC; idx += blockDim.x) {
            int o = idx >> 6, c = idx & 63;
            Ks[o * 65 + c] = KN[(size_t)(ot * NC + o) * NC + c];
        }
        __syncthreads();

        if (node < n) {
            float acc[NC];
#pragma unroll
            for (int o = 0; o < NC; o++) acc[o] = 0.0f;

            const float* xr = x + (size_t)node * NC;
#pragma unroll 8
            for (int c = 0; c < NC; c++) {
                float xv = __ldg(&xr[c]);
#pragma unroll
                for (int o = 0; o < NC; o++)
                    acc[o] = fmaf(Ks[o * 65 + c], xv, acc[o]);
            }
#pragma unroll
            for (int o = 0; o < NC; o++)
                out[(size_t)(ot * NC + o) * n + node] = acc[o];
        }
        __syncthreads();
    }
}

// ---------------------------------------------------------------------------
// launch
// ---------------------------------------------------------------------------
extern "C" void kernel_launch(void* const* d_in, const int* in_sizes, int n_in,
                              void* d_out, int out_size) {
    const float* xn  = (const float*)d_in[0];   // [1,128,N]
    const int* ei    = (const int*)d_in[1];     // [E]
    const int* ej    = (const int*)d_in[2];     // [E]
    const float* K1  = (const float*)d_in[3];   // [64,128]
    const float* KN1 = (const float*)d_in[4];   // [4,64,64]
    const float* KNc = (const float*)d_in[5];   // [1024,64]
    float* out = (float*)d_out;

    int n = in_sizes[0] / CIN;   // 50000
    int e = in_sizes[1];         // 800000

    int nb_n = (n + 255) / 256;
    int nb_e = (e + 255) / 256;

    k_init<<<nb_n, 256>>>(n);
    k_edge_count<<<nb_e, 256>>>(ei, ej, e);
    k_dinv2<<<nb_n, 256>>>(n);
    k_scan<<<1, 1024>>>(n);
    k_fill<<<nb_e, 256>>>(ei, ej, e);
    k_open<<<nb_n, 256>>>(xn, K1, n);

    // buffer rotation: (cur, prev, next)
    // step0: A,B->C   step1: C,A->B   step2: B,C->A   step3: A,B->C
    const int rot[NSTEPS][3] = { {0,1,2}, {2,0,1}, {1,2,0}, {0,1,2} };
    for (int s = 0; s < NSTEPS; s++) {
        k_step<<<1184, 256>>>(rot[s][0], rot[s][1], rot[s][2], KN1 + (size_t)s * NC * NC, n);
    }
    // final x lives in buffer 2 (g_xc)
    k_close<<<nb_n, 256>>>(2, KNc, out, n);
}

// round 5
// speedup vs baseline: 1.4449x; 1.4449x over previous
#include <cuda_runtime.h>
#include <math.h>

// Problem constants (match reference_code)
#define NN 50000
#define NE 800000
#define NC 64          // hidden channels
#define CIN 128        // input channels
#define COUT 1024      // output channels
#define NSTEPS 4
#define H2 0.01f       // H*H, H=0.1
#define NBLK 196       // ceil(NN/256)

// ---------------------------------------------------------------------------
// Scratch (no allocations allowed -> __device__ globals).
// Total ~45.9 MB -- kept at/below the round-1 footprint that passed the
// harness memory checkpoint. State stored SCALED: y = dinv2 * x.
// ---------------------------------------------------------------------------
__device__ float g_deg[NN];
__device__ float g_dinv2[NN + 1];     // [NN] = 0 (pad)
__device__ float g_ssum[NN];
__device__ int   g_cnt[NN];           // reused as cursor after scan
__device__ int   g_rowptr[NN + 1];
__device__ int   g_bsum[NBLK];
__device__ int   g_boff[NBLK];
__device__ int   g_adj[2 * NE];
__device__ float g_ya[(size_t)NC * (NN + 1)];  // scaled state, row NN = zeros
__device__ float g_yb[(size_t)NC * (NN + 1)];
__device__ float g_yc[(size_t)NC * (NN + 1)];

__device__ __forceinline__ float* buf_sel(int w) {
    return (w == 0) ? g_ya : ((w == 1) ? g_yb : g_yc);
}

__device__ __forceinline__ float tanh_fast(float x) {
    float r;
    asm("tanh.approx.f32 %0, %1;" : "=f"(r) : "f"(x));
    return r;
}

// ---------------------------------------------------------------------------
// 1) init: deg = 1 (self loop), cnt = 0, zero pad rows of y buffers
// ---------------------------------------------------------------------------
__global__ void k_init(int n) {
    int i = blockIdx.x * blockDim.x + threadIdx.x;
    if (i < n) {
        g_deg[i] = 1.0f;
        g_cnt[i] = 0;
    }
    if (i < NC) {
        g_ya[(size_t)NN * NC + i] = 0.0f;
        g_yb[(size_t)NN * NC + i] = 0.0f;
        g_yc[(size_t)NN * NC + i] = 0.0f;
    }
}

// ---------------------------------------------------------------------------
// 2) per-edge: deg histogram over J, incidence counts for CSR
// ---------------------------------------------------------------------------
__global__ void k_count(const int* __restrict__ ei, const int* __restrict__ ej, int e) {
    int k = blockIdx.x * blockDim.x + threadIdx.x;
    if (k < e) {
        int i = ei[k], j = ej[k];
        atomicAdd(&g_deg[j], 1.0f);
        atomicAdd(&g_cnt[i], 1);
        atomicAdd(&g_cnt[j], 1);
    }
}

// ---------------------------------------------------------------------------
// 3) dinv2 = 1/deg + per-block sums of cnt (coalesced)
// ---------------------------------------------------------------------------
__global__ void k_bsum(int n) {
    __shared__ int s[256];
    int t = threadIdx.x;
    int i = blockIdx.x * 256 + t;
    int v = 0;
    if (i < n) {
        g_dinv2[i] = 1.0f / g_deg[i];
        v = g_cnt[i];
    } else if (i <= NN) {
        g_dinv2[i] = 0.0f;  // pad entry
    }
    s[t] = v;
    __syncthreads();
    for (int off = 128; off > 0; off >>= 1) {
        if (t < off) s[t] += s[t + off];
        __syncthreads();
    }
    if (t == 0) g_bsum[blockIdx.x] = s[0];
}

// ---------------------------------------------------------------------------
// 4) scan of block sums (1 block)
// ---------------------------------------------------------------------------
__global__ void k_bscan(int n) {
    __shared__ int s[256];
    int t = threadIdx.x;
    int v = (t < NBLK) ? g_bsum[t] : 0;
    s[t] = v;
    __syncthreads();
    for (int off = 1; off < 256; off <<= 1) {
        int x = 0;
        if (t >= off) x = s[t - off];
        __syncthreads();
        s[t] += x;
        __syncthreads();
    }
    if (t < NBLK) g_boff[t] = s[t] - v;
    if (t == 0) g_rowptr[n] = s[255];
}

// ---------------------------------------------------------------------------
// 5) per-block scan of cnt -> rowptr; g_cnt becomes the fill cursor
// ---------------------------------------------------------------------------
__global__ void k_rowfill(int n) {
    __shared__ int s[256];
    int t = threadIdx.x;
    int i = blockIdx.x * 256 + t;
    int v = (i < n) ? g_cnt[i] : 0;
    s[t] = v;
    __syncthreads();
    for (int off = 1; off < 256; off <<= 1) {
        int x = 0;
        if (t >= off) x = s[t - off];
        __syncthreads();
        s[t] += x;
        __syncthreads();
    }
    if (i < n) {
        int rp = g_boff[blockIdx.x] + s[t] - v;
        g_rowptr[i] = rp;
        g_cnt[i] = rp;   // cursor
    }
}

// ---------------------------------------------------------------------------
// 6) fill undirected adjacency (cursor = g_cnt)
// ---------------------------------------------------------------------------
__global__ void k_fill(const int* __restrict__ ei, const int* __restrict__ ej, int e) {
    int k = blockIdx.x * blockDim.x + threadIdx.x;
    if (k < e) {
        int i = ei[k], j = ej[k];
        int p = atomicAdd(&g_cnt[i], 1);
        g_adj[p] = j;
        int q = atomicAdd(&g_cnt[j], 1);
        g_adj[q] = i;
    }
}

// ---------------------------------------------------------------------------
// 7) ssum[n] = sum over neighbors m of dinv2[m]   (constant across steps)
// ---------------------------------------------------------------------------
__global__ void k_ssum(int n) {
    int gw = (blockIdx.x * blockDim.x + threadIdx.x) >> 5;
    int lane = threadIdx.x & 31;
    if (gw >= n) return;
    int r0 = g_rowptr[gw], r1 = g_rowptr[gw + 1];
    float s = 0.0f;
    for (int k = r0 + lane; k < r1; k += 32) s += g_dinv2[g_adj[k]];
#pragma unroll
    for (int o = 16; o; o >>= 1) s += __shfl_xor_sync(0xffffffffu, s, o);
    if (lane == 0) g_ssum[gw] = s;
}

// ---------------------------------------------------------------------------
// 8) opening: x0[n,o] = relu( sum_c K1[o,c] * xn[c,n] ); store y0 = dinv2*x0
//    into buffers 0 and 1. blockIdx.y splits outputs into 2x32 channels.
// ---------------------------------------------------------------------------
__global__ void __launch_bounds__(256) k_open(const float* __restrict__ xn,
                                              const float* __restrict__ K1, int n) {
    __shared__ float Ks[32 * CIN];  // 16KB
    int obase = blockIdx.y * 32;
    for (int idx = threadIdx.x; idx < 32 * CIN; idx += 256)
        Ks[idx] = K1[(size_t)obase * CIN + idx];
    __syncthreads();

    int node = blockIdx.x * 256 + threadIdx.x;
    if (node >= n) return;

    float acc[32];
#pragma unroll
    for (int o = 0; o < 32; o++) acc[o] = 0.0f;

#pragma unroll 4
    for (int c = 0; c < CIN; c++) {
        float xv = xn[(size_t)c * n + node];
#pragma unroll
        for (int o = 0; o < 32; o++)
            acc[o] = fmaf(Ks[o * CIN + c], xv, acc[o]);
    }

    float di = g_dinv2[node];
    size_t nb = (size_t)node * NC + obase;
#pragma unroll
    for (int j = 0; j < 8; j++) {
        float4 v;
        v.x = di * fmaxf(acc[4 * j + 0], 0.0f);
        v.y = di * fmaxf(acc[4 * j + 1], 0.0f);
        v.z = di * fmaxf(acc[4 * j + 2], 0.0f);
        v.w = di * fmaxf(acc[4 * j + 3], 0.0f);
        *(float4*)&g_ya[nb + 4 * j] = v;
        *(float4*)&g_yb[nb + 4 * j] = v;
    }
}

// ---------------------------------------------------------------------------
// 9) fused wave step on scaled state y = dinv2*x:
//    acc[c]  = sum_m y[m,c]
//    x       = y*deg;  lap[c] = dinv2*(ssum*x - acc[c])
//    x_next  = 2x - x_prev - H2*tanh(K @ lap);  y_next = dinv2*x_next
// ---------------------------------------------------------------------------
__global__ void __launch_bounds__(256) k_step(int wcur, int wprev, int wnext,
                                              const float* __restrict__ K, int n) {
    __shared__ float Ks[NC * 65];
    __shared__ float laps[8][NC];

    const float* yc = buf_sel(wcur);
    const float* yp = buf_sel(wprev);
    float* yo = buf_sel(wnext);

    for (int idx = threadIdx.x; idx < NC * NC; idx += 256)
        Ks[(idx >> 6) * 65 + (idx & 63)] = K[idx];
    __syncthreads();

    int warp = threadIdx.x >> 5;
    int lane = threadIdx.x & 31;

    for (int base = blockIdx.x * 8; base < n; base += gridDim.x * 8) {
        int node = base + warp;
        if (node < n) {
            size_t nb = (size_t)node * NC;
            float dg = g_deg[node];
            float di = g_dinv2[node];
            float sv = g_ssum[node];
            float x0 = yc[nb + lane] * dg;
            float x1 = yc[nb + 32 + lane] * dg;
            int r0 = g_rowptr[node];
            int r1 = g_rowptr[node + 1];

            float acc0 = 0.0f, acc1 = 0.0f;
            for (int kk = r0; kk < r1; kk += 32) {
                int idx = kk + lane;
                int a = (idx < r1) ? g_adj[idx] : NN;   // NN -> zero row
                int cnt = r1 - kk; if (cnt > 32) cnt = 32;
                for (int t8 = 0; t8 < cnt; t8 += 8) {
#pragma unroll
                    for (int u = 0; u < 8; u++) {
                        int m = __shfl_sync(0xffffffffu, a, t8 + u);
                        const float* yr = yc + ((size_t)m << 6);
                        acc0 += yr[lane];
                        acc1 += yr[32 + lane];
                    }
                }
            }
            float lap0 = di * fmaf(sv, x0, -acc0);
            float lap1 = di * fmaf(sv, x1, -acc1);

            laps[warp][lane] = lap0;
            laps[warp][lane + 32] = lap1;
            __syncwarp();

            float t0 = 0.0f, t1 = 0.0f;
#pragma unroll
            for (int c = 0; c < NC; c++) {
                float lv = laps[warp][c];
                t0 = fmaf(Ks[lane * 65 + c], lv, t0);
                t1 = fmaf(Ks[(lane + 32) * 65 + c], lv, t1);
            }
            __syncwarp();

            float xp0 = yp[nb + lane] * dg;
            float xp1 = yp[nb + 32 + lane] * dg;
            float n0 = fmaf(2.0f, x0, -xp0) - H2 * tanh_fast(t0);
            float n1 = fmaf(2.0f, x1, -xp1) - H2 * tanh_fast(t1);
            yo[nb + lane] = di * n0;
            yo[nb + 32 + lane] = di * n1;
        }
    }
}

// ---------------------------------------------------------------------------
// 10) transpose + unscale: xT[c][node] = y[node][c] * deg[node]
//     src/dst passed as buffer selectors (device-side resolution).
// ---------------------------------------------------------------------------
__global__ void k_transpose(int wsrc, int wdst, int n) {
    __shared__ float s[32][33];
    const float* y = buf_sel(wsrc);
    float* xT = buf_sel(wdst);
    int c0 = blockIdx.y * 32;
    int n0 = blockIdx.x * 32;
    int tx = threadIdx.x, ty = threadIdx.y;  // 32 x 8
#pragma unroll
    for (int k = 0; k < 32; k += 8) {
        int node = n0 + ty + k;
        float v = 0.0f;
        if (node < n) v = y[(size_t)node * NC + c0 + tx] * g_deg[node];
        s[ty + k][tx] = v;
    }
    __syncthreads();
#pragma unroll
    for (int k = 0; k < 32; k += 8) {
        int node = n0 + tx;
        int c = c0 + ty + k;
        if (node < n) xT[(size_t)c * n + node] = s[tx][ty + k];
    }
}

// ---------------------------------------------------------------------------
// 11) closing projection: out[o,n] = sum_c KNclose[o,c] * x[n,c]
//     scalar FMA, 32 o-tiles of 32 outputs; xT coalesced reads; acc = 32 regs.
// ---------------------------------------------------------------------------
__global__ void __launch_bounds__(256) k_close(int wsrc,
                                               const float* __restrict__ KN,
                                               float* __restrict__ out, int n) {
    __shared__ float Ks[32 * NC];  // 8KB
    const float* xT = buf_sel(wsrc);
    int obase = blockIdx.y * 32;
    for (int idx = threadIdx.x; idx < 32 * NC; idx += 256)
        Ks[idx] = KN[(size_t)obase * NC + idx];
    __syncthreads();

    int node = blockIdx.x * 256 + threadIdx.x;
    if (node >= n) return;

    float acc[32];
#pragma unroll
    for (int o = 0; o < 32; o++) acc[o] = 0.0f;

#pragma unroll 4
    for (int c = 0; c < NC; c++) {
        float xv = xT[(size_t)c * n + node];
#pragma unroll
        for (int o = 0; o < 32; o++)
            acc[o] = fmaf(Ks[o * NC + c], xv, acc[o]);
    }
#pragma unroll
    for (int o = 0; o < 32; o++)
        out[(size_t)(obase + o) * n + node] = acc[o];
}

// ---------------------------------------------------------------------------
// launch (NOTE: host code never references __device__ symbols)
// ---------------------------------------------------------------------------
extern "C" void kernel_launch(void* const* d_in, const int* in_sizes, int n_in,
                              void* d_out, int out_size) {
    const float* xn  = (const float*)d_in[0];   // [1,128,N]
    const int* ei    = (const int*)d_in[1];     // [E]
    const int* ej    = (const int*)d_in[2];     // [E]
    const float* K1  = (const float*)d_in[3];   // [64,128]
    const float* KN1 = (const float*)d_in[4];   // [4,64,64]
    const float* KNc = (const float*)d_in[5];   // [1024,64]
    float* out = (float*)d_out;

    int n = in_sizes[0] / CIN;   // 50000
    int e = in_sizes[1];         // 800000

    int nb_n = (n + 255) / 256;  // 196
    int nb_e = (e + 255) / 256;

    k_init<<<nb_n, 256>>>(n);
    k_count<<<nb_e, 256>>>(ei, ej, e);
    k_bsum<<<nb_n, 256>>>(n);
    k_bscan<<<1, 256>>>(n);
    k_rowfill<<<nb_n, 256>>>(n);
    k_fill<<<nb_e, 256>>>(ei, ej, e);
    k_ssum<<<(n * 32 + 255) / 256, 256>>>(n);
    k_open<<<dim3(nb_n, 2), 256>>>(xn, K1, n);

    // rotation (cur, prev, next):
    // s0: 0,1->2 | s1: 2,0->1 | s2: 1,2->0 | s3: 0,1->2   (final in 2)
    const int rot[NSTEPS][3] = { {0,1,2}, {2,0,1}, {1,2,0}, {0,1,2} };
    for (int s = 0; s < NSTEPS; s++) {
        k_step<<<592, 256>>>(rot[s][0], rot[s][1], rot[s][2],
                             KN1 + (size_t)s * NC * NC, n);
    }
    // final y in buffer 2; transpose+unscale into buffer 1 (retired), then close
    k_transpose<<<dim3((n + 31) / 32, 2), dim3(32, 8)>>>(2, 1, n);
    k_close<<<dim3(nb_n, 32), 256>>>(1, KNc, out, n);
}

// round 6
// speedup vs baseline: 1.9625x; 1.3583x over previous
#include <cuda_runtime.h>
#include <math.h>

// Problem constants (match reference_code)
#define NN 50000
#define NE 800000
#define NC 64          // hidden channels
#define CIN 128        // input channels
#define COUT 1024      // output channels
#define NSTEPS 4
#define H2 0.01f       // H*H, H=0.1
#define NBLK 196       // ceil(NN/256)

typedef unsigned long long u64;

// ---------------------------------------------------------------------------
// Scratch (no allocations allowed -> __device__ globals). ~45.9 MB total.
// State stored SCALED: y = dinv2 * x   (x recovered as y*deg).
// ---------------------------------------------------------------------------
__device__ float g_deg[NN];
__device__ float g_dinv2[NN + 1];     // [NN] = 0 (pad)
__device__ float g_ssum[NN];
__device__ int   g_cnt[NN];           // reused as cursor after scan
__device__ int   g_rowptr[NN + 1];
__device__ int   g_bsum[NBLK];
__device__ int   g_boff[NBLK];
__device__ int   g_adj[2 * NE];
__device__ float g_ya[(size_t)NC * (NN + 1)];  // scaled state, row NN = zeros
__device__ float g_yb[(size_t)NC * (NN + 1)];
__device__ float g_yc[(size_t)NC * (NN + 1)];

__device__ __forceinline__ float* buf_sel(int w) {
    return (w == 0) ? g_ya : ((w == 1) ? g_yb : g_yc);
}

// ---------------------------------------------------------------------------
// packed f32x2 helpers (sm_100a)
// ---------------------------------------------------------------------------
#define FMA2(d, a, b, c) \
    asm("fma.rn.f32x2 %0, %1, %2, %3;" : "=l"(d) : "l"(a), "l"(b), "l"(c))
#define ADD2(d, a, b) \
    asm("add.rn.f32x2 %0, %1, %2;" : "=l"(d) : "l"(a), "l"(b))
#define MUL2(d, a, b) \
    asm("mul.rn.f32x2 %0, %1, %2;" : "=l"(d) : "l"(a), "l"(b))

__device__ __forceinline__ u64 pk2(float lo, float hi) {
    u64 r;
    asm("mov.b64 %0, {%1, %2};" : "=l"(r) : "f"(lo), "f"(hi));
    return r;
}
__device__ __forceinline__ float2 upk2(u64 v) {
    float2 r;
    asm("mov.b64 {%0, %1}, %2;" : "=f"(r.x), "=f"(r.y) : "l"(v));
    return r;
}
__device__ __forceinline__ float tanh_fast(float x) {
    float r;
    asm("tanh.approx.f32 %0, %1;" : "=f"(r) : "f"(x));
    return r;
}

// ---------------------------------------------------------------------------
// 1) init
// ---------------------------------------------------------------------------
__global__ void k_init(int n) {
    int i = blockIdx.x * blockDim.x + threadIdx.x;
    if (i < n) {
        g_deg[i] = 1.0f;
        g_cnt[i] = 0;
    }
    if (i < NC) {
        g_ya[(size_t)NN * NC + i] = 0.0f;
        g_yb[(size_t)NN * NC + i] = 0.0f;
        g_yc[(size_t)NN * NC + i] = 0.0f;
    }
}

// ---------------------------------------------------------------------------
// 2) per-edge: deg histogram over J, incidence counts for CSR
// ---------------------------------------------------------------------------
__global__ void k_count(const int* __restrict__ ei, const int* __restrict__ ej, int e) {
    int k = blockIdx.x * blockDim.x + threadIdx.x;
    if (k < e) {
        int i = ei[k], j = ej[k];
        atomicAdd(&g_deg[j], 1.0f);
        atomicAdd(&g_cnt[i], 1);
        atomicAdd(&g_cnt[j], 1);
    }
}

// ---------------------------------------------------------------------------
// 3) dinv2 = 1/deg + per-block sums of cnt
// ---------------------------------------------------------------------------
__global__ void k_bsum(int n) {
    __shared__ int s[256];
    int t = threadIdx.x;
    int i = blockIdx.x * 256 + t;
    int v = 0;
    if (i < n) {
        g_dinv2[i] = 1.0f / g_deg[i];
        v = g_cnt[i];
    } else if (i <= NN) {
        g_dinv2[i] = 0.0f;  // pad entry
    }
    s[t] = v;
    __syncthreads();
    for (int off = 128; off > 0; off >>= 1) {
        if (t < off) s[t] += s[t + off];
        __syncthreads();
    }
    if (t == 0) g_bsum[blockIdx.x] = s[0];
}

// ---------------------------------------------------------------------------
// 4) scan of block sums (1 block)
// ---------------------------------------------------------------------------
__global__ void k_bscan(int n) {
    __shared__ int s[256];
    int t = threadIdx.x;
    int v = (t < NBLK) ? g_bsum[t] : 0;
    s[t] = v;
    __syncthreads();
    for (int off = 1; off < 256; off <<= 1) {
        int x = 0;
        if (t >= off) x = s[t - off];
        __syncthreads();
        s[t] += x;
        __syncthreads();
    }
    if (t < NBLK) g_boff[t] = s[t] - v;
    if (t == 0) g_rowptr[n] = s[255];
}

// ---------------------------------------------------------------------------
// 5) per-block scan of cnt -> rowptr; g_cnt becomes the fill cursor
// ---------------------------------------------------------------------------
__global__ void k_rowfill(int n) {
    __shared__ int s[256];
    int t = threadIdx.x;
    int i = blockIdx.x * 256 + t;
    int v = (i < n) ? g_cnt[i] : 0;
    s[t] = v;
    __syncthreads();
    for (int off = 1; off < 256; off <<= 1) {
        int x = 0;
        if (t >= off) x = s[t - off];
        __syncthreads();
        s[t] += x;
        __syncthreads();
    }
    if (i < n) {
        int rp = g_boff[blockIdx.x] + s[t] - v;
        g_rowptr[i] = rp;
        g_cnt[i] = rp;   // cursor
    }
}

// ---------------------------------------------------------------------------
// 6) fill undirected adjacency (cursor = g_cnt)
// ---------------------------------------------------------------------------
__global__ void k_fill(const int* __restrict__ ei, const int* __restrict__ ej, int e) {
    int k = blockIdx.x * blockDim.x + threadIdx.x;
    if (k < e) {
        int i = ei[k], j = ej[k];
        int p = atomicAdd(&g_cnt[i], 1);
        g_adj[p] = j;
        int q = atomicAdd(&g_cnt[j], 1);
        g_adj[q] = i;
    }
}

// ---------------------------------------------------------------------------
// 7) ssum[n] = sum over neighbors m of dinv2[m]
// ---------------------------------------------------------------------------
__global__ void k_ssum(int n) {
    int gw = (blockIdx.x * blockDim.x + threadIdx.x) >> 5;
    int lane = threadIdx.x & 31;
    if (gw >= n) return;
    int r0 = g_rowptr[gw], r1 = g_rowptr[gw + 1];
    float s = 0.0f;
    for (int k = r0 + lane; k < r1; k += 32) s += g_dinv2[g_adj[k]];
#pragma unroll
    for (int o = 16; o; o >>= 1) s += __shfl_xor_sync(0xffffffffu, s, o);
    if (lane == 0) g_ssum[gw] = s;
}

// ---------------------------------------------------------------------------
// 8) opening: x0[n,o] = relu( sum_c K1[o,c] * xn[c,n] ); store y0 = dinv2*x0
//    blockIdx.y splits outputs into 2x32; packed output pairs (16 u64 accs).
// ---------------------------------------------------------------------------
__global__ void __launch_bounds__(256) k_open(const float* __restrict__ xn,
                                              const float* __restrict__ K1, int n) {
    __shared__ u64 Ksp[CIN * 16];  // 16KB: Ksp[c*16+op] = (K1[ob+2op][c], K1[ob+2op+1][c])
    int obase = blockIdx.y * 32;
    for (int idx = threadIdx.x; idx < CIN * 16; idx += 256) {
        int c = idx >> 4, op = idx & 15;
        Ksp[idx] = pk2(K1[(obase + 2 * op) * CIN + c],
                       K1[(obase + 2 * op + 1) * CIN + c]);
    }
    __syncthreads();

    int node = blockIdx.x * 256 + threadIdx.x;
    if (node >= n) return;

    u64 acc[16];
#pragma unroll
    for (int j = 0; j < 16; j++) acc[j] = 0ull;

#pragma unroll 2
    for (int c = 0; c < CIN; c++) {
        float xv = xn[(size_t)c * n + node];
        u64 xv2 = pk2(xv, xv);
        const u64* kp = &Ksp[c * 16];
#pragma unroll
        for (int j = 0; j < 16; j++)
            FMA2(acc[j], kp[j], xv2, acc[j]);
    }

    float di = g_dinv2[node];
    size_t nb = (size_t)node * NC + obase;
#pragma unroll
    for (int j = 0; j < 8; j++) {
        float2 p0 = upk2(acc[2 * j]);
        float2 p1 = upk2(acc[2 * j + 1]);
        float4 v;
        v.x = di * fmaxf(p0.x, 0.0f);
        v.y = di * fmaxf(p0.y, 0.0f);
        v.z = di * fmaxf(p1.x, 0.0f);
        v.w = di * fmaxf(p1.y, 0.0f);
        *(float4*)&g_ya[nb + 4 * j] = v;
        *(float4*)&g_yb[nb + 4 * j] = v;
    }
}

// ---------------------------------------------------------------------------
// 9) fused wave step, fully packed. Lane owns channel pair (2L, 2L+1).
//    acc2 = sum_m y[m, pair]        (1 LDG.64 + 1 ADD2 per neighbor)
//    x2 = y2*deg; lap2 = di*(ssum*x2 - acc2)
//    t2[o-pair] = sum_c Kpair[c] * lap[c]   (LDS.64 + FMA2)
//    x_next = 2x - x_prev - H2*tanh(t); y_next = di*x_next
// ---------------------------------------------------------------------------
__global__ void __launch_bounds__(256) k_step(int wcur, int wprev, int wnext,
                                              const float* __restrict__ K, int n) {
    __shared__ u64 Ksp[NC * 32];     // 16KB: Ksp[c*32+L] = (K[2L][c], K[2L+1][c])
    __shared__ float laps[8][NC];

    const float* yc = buf_sel(wcur);
    const float* yp = buf_sel(wprev);
    float* yo = buf_sel(wnext);
    const u64* ycp = (const u64*)yc;
    const u64* ypp = (const u64*)yp;
    u64* yop = (u64*)yo;

    for (int idx = threadIdx.x; idx < NC * 32; idx += 256) {
        int c = idx >> 5, L = idx & 31;
        Ksp[idx] = pk2(K[(2 * L) * NC + c], K[(2 * L + 1) * NC + c]);
    }
    __syncthreads();

    int warp = threadIdx.x >> 5;
    int lane = threadIdx.x & 31;
    const u64 signmask = 0x8000000080000000ull;

    for (int base = blockIdx.x * 8; base < n; base += gridDim.x * 8) {
        int node = base + warp;
        if (node < n) {
            size_t nb32 = (size_t)node << 5;  // row offset in u64 units
            float dg = g_deg[node];
            float di = g_dinv2[node];
            float sv = g_ssum[node];
            u64 dg2 = pk2(dg, dg);
            u64 di2 = pk2(di, di);
            u64 sv2 = pk2(sv, sv);

            u64 yv = ycp[nb32 + lane];
            u64 x2; MUL2(x2, yv, dg2);

            int r0 = g_rowptr[node];
            int r1 = g_rowptr[node + 1];

            u64 acc2 = 0ull;
            for (int kk = r0; kk < r1; kk += 32) {
                int idx = kk + lane;
                int a = (idx < r1) ? g_adj[idx] : NN;   // NN -> zero row
                int cnt = r1 - kk; if (cnt > 32) cnt = 32;
                for (int t8 = 0; t8 < cnt; t8 += 8) {
#pragma unroll
                    for (int u = 0; u < 8; u++) {
                        int m = __shfl_sync(0xffffffffu, a, t8 + u);
                        u64 v = ycp[((size_t)m << 5) + lane];
                        ADD2(acc2, acc2, v);
                    }
                }
            }
            // lap2 = di * (sv*x2 - acc2)
            u64 nacc = acc2 ^ signmask;
            u64 tmp; FMA2(tmp, sv2, x2, nacc);
            u64 lap2; MUL2(lap2, di2, tmp);
            ((float2*)laps[warp])[lane] = upk2(lap2);
            __syncwarp();

            // matvec: outputs (2*lane, 2*lane+1)
            u64 t2 = 0ull;
#pragma unroll
            for (int c = 0; c < NC; c++) {
                float lv = laps[warp][c];       // broadcast
                u64 lv2 = pk2(lv, lv);
                FMA2(t2, Ksp[c * 32 + lane], lv2, t2);
            }
            __syncwarp();

            float2 tt = upk2(t2);
            u64 d2 = pk2(tanh_fast(tt.x), tanh_fast(tt.y));

            u64 xpv = ypp[nb32 + lane];
            u64 xp2; MUL2(xp2, xpv, dg2);
            // n2 = 2*x2 - xp2 - H2*d2
            u64 two2 = pk2(2.0f, 2.0f);
            u64 nH2 = pk2(-H2, -H2);
            u64 n2; FMA2(n2, two2, x2, xp2 ^ signmask);
            FMA2(n2, nH2, d2, n2);
            u64 yout; MUL2(yout, di2, n2);
            yop[nb32 + lane] = yout;
        }
    }
}

// ---------------------------------------------------------------------------
// 10) transpose + unscale: xT[c][node] = y[node][c] * deg[node]
// ---------------------------------------------------------------------------
__global__ void k_transpose(int wsrc, int wdst, int n) {
    __shared__ float s[32][33];
    const float* y = buf_sel(wsrc);
    float* xT = buf_sel(wdst);
    int c0 = blockIdx.y * 32;
    int n0 = blockIdx.x * 32;
    int tx = threadIdx.x, ty = threadIdx.y;  // 32 x 8
#pragma unroll
    for (int k = 0; k < 32; k += 8) {
        int node = n0 + ty + k;
        float v = 0.0f;
        if (node < n) v = y[(size_t)node * NC + c0 + tx] * g_deg[node];
        s[ty + k][tx] = v;
    }
    __syncthreads();
#pragma unroll
    for (int k = 0; k < 32; k += 8) {
        int node = n0 + tx;
        int c = c0 + ty + k;
        if (node < n) xT[(size_t)c * n + node] = s[tx][ty + k];
    }
}

// ---------------------------------------------------------------------------
// 11) closing projection: out[o,n] = sum_c KNclose[o,c] * x[n,c]
//     packed output pairs: 16 u64 accs per 32-output tile; xT coalesced.
// ---------------------------------------------------------------------------
__global__ void __launch_bounds__(256) k_close(int wsrc,
                                               const float* __restrict__ KN,
                                               float* __restrict__ out, int n) {
    __shared__ u64 Ksp[NC * 16];   // 8KB: Ksp[c*16+op] = (KN[ob+2op][c], KN[ob+2op+1][c])
    const float* xT = buf_sel(wsrc);
    int obase = blockIdx.y * 32;
    for (int idx = threadIdx.x; idx < NC * 16; idx += 256) {
        int c = idx >> 4, op = idx & 15;
        Ksp[idx] = pk2(KN[(size_t)(obase + 2 * op) * NC + c],
                       KN[(size_t)(obase + 2 * op + 1) * NC + c]);
    }
    __syncthreads();

    int node = blockIdx.x * 256 + threadIdx.x;
    if (node >= n) return;

    u64 acc[16];
#pragma unroll
    for (int op = 0; op < 16; op++) acc[op] = 0ull;

#pragma unroll 2
    for (int c = 0; c < NC; c++) {
        float xv = xT[(size_t)c * n + node];
        u64 xv2 = pk2(xv, xv);
        const u64* kp = &Ksp[c * 16];
#pragma unroll
        for (int op = 0; op < 16; op++)
            FMA2(acc[op], kp[op], xv2, acc[op]);
    }
#pragma unroll
    for (int op = 0; op < 16; op++) {
        float2 p = upk2(acc[op]);
        out[(size_t)(obase + 2 * op) * n + node] = p.x;
        out[(size_t)(obase + 2 * op + 1) * n + node] = p.y;
    }
}

// ---------------------------------------------------------------------------
// launch (host code never references __device__ symbols)
// ---------------------------------------------------------------------------
extern "C" void kernel_launch(void* const* d_in, const int* in_sizes, int n_in,
                              void* d_out, int out_size) {
    const float* xn  = (const float*)d_in[0];   // [1,128,N]
    const int* ei    = (const int*)d_in[1];     // [E]
    const int* ej    = (const int*)d_in[2];     // [E]
    const float* K1  = (const float*)d_in[3];   // [64,128]
    const float* KN1 = (const float*)d_in[4];   // [4,64,64]
    const float* KNc = (const float*)d_in[5];   // [1024,64]
    float* out = (float*)d_out;

    int n = in_sizes[0] / CIN;   // 50000
    int e = in_sizes[1];         // 800000

    int nb_n = (n + 255) / 256;  // 196
    int nb_e = (e + 255) / 256;

    k_init<<<nb_n, 256>>>(n);
    k_count<<<nb_e, 256>>>(ei, ej, e);
    k_bsum<<<nb_n, 256>>>(n);
    k_bscan<<<1, 256>>>(n);
    k_rowfill<<<nb_n, 256>>>(n);
    k_fill<<<nb_e, 256>>>(ei, ej, e);
    k_ssum<<<(n * 32 + 255) / 256, 256>>>(n);
    k_open<<<dim3(nb_n, 2), 256>>>(xn, K1, n);

    // rotation (cur, prev, next):
    // s0: 0,1->2 | s1: 2,0->1 | s2: 1,2->0 | s3: 0,1->2   (final in 2)
    const int rot[NSTEPS][3] = { {0,1,2}, {2,0,1}, {1,2,0}, {0,1,2} };
    for (int s = 0; s < NSTEPS; s++) {
        k_step<<<592, 256>>>(rot[s][0], rot[s][1], rot[s][2],
                             KN1 + (size_t)s * NC * NC, n);
    }
    // final y in buffer 2; transpose+unscale into buffer 1 (retired), then close
    k_transpose<<<dim3((n + 31) / 32, 2), dim3(32, 8)>>>(2, 1, n);
    k_close<<<dim3(nb_n, 32), 256>>>(1, KNc, out, n);
}